// round 12
// baseline (speedup 1.0000x reference)
#include <cuda_runtime.h>
#include <cuda_bf16.h>

#define KNB 32
#define INVALID_KEY 0xFFFFFFFFFFFFFFFFull
#define FULLMASK 0xFFFFFFFFu
// exact d2 threshold: dist<=5.0 with dist=__fsqrt_rn(d2)  <=>  d2 <= 25+2^-19
#define D2_THRESH_BITS 0x41C80001u

typedef unsigned long long u64;

// XLA-matching sum of squares: rn(rn(rn(x^2)+rn(y^2))+rn(z^2)), NO fma fusion
__device__ __forceinline__ float sumsq_xla(float x, float y, float z) {
    return __fadd_rn(__fadd_rn(__fmul_rn(x, x), __fmul_rn(y, y)), __fmul_rn(z, z));
}

__device__ __forceinline__ u64 shfl_xor64(u64 v, int m) { return __shfl_xor_sync(FULLMASK, v, m); }

// dual warp-parallel 32-ary search, both searches issued per round:
//   LO = first idx with batch[idx] >= b0   (lower bound)
//   HI = first idx with batch[idx] >  b1   (upper bound)
__device__ __forceinline__ int2 warp_bound_dual(const int* __restrict__ batch, int N,
                                                int b0, int b1, int lane) {
    int l0 = 0, w0 = N, l1 = 0, w1 = N;
    while (w0 > 0 || w1 > 0) {
        int step0 = (w0 + 31) >> 5;
        int step1 = (w1 + 31) >> 5;
        int off0 = lane * step0;
        int off1 = lane * step1;
        bool in0 = (w0 > 0) && (off0 < w0);
        bool in1 = (w1 > 0) && (off1 < w1);
        int m0 = l0 + (in0 ? off0 : 0);
        int m1 = l1 + (in1 ? off1 : 0);
        int v0 = batch[m0];          // both probes in flight together
        int v1 = batch[m1];
        unsigned bal0 = __ballot_sync(FULLMASK, in0 && (v0 < b0));
        unsigned bal1 = __ballot_sync(FULLMASK, in1 && (v1 <= b1));
        if (w0 > 0) {
            int c = __popc(bal0);
            if (c == 0) w0 = 0;
            else {
                int newl = l0 + (c - 1) * step0 + 1;
                int ub = (c * step0 < w0) ? (l0 + c * step0) : (l0 + w0);
                w0 = ub - newl; l0 = newl;
            }
        }
        if (w1 > 0) {
            int c = __popc(bal1);
            if (c == 0) w1 = 0;
            else {
                int newl = l1 + (c - 1) * step1 + 1;
                int ub = (c * step1 < w1) ? (l1 + c * step1) : (l1 + w1);
                w1 = ub - newl; l1 = newl;
            }
        }
    }
    return make_int2(l0, l1);
}

// full bitonic sort of 32 keys, ascending by lane
__device__ __forceinline__ void bitonic_sort32(u64& v, int lane) {
#pragma unroll
    for (int k = 2; k <= 32; k <<= 1) {
#pragma unroll
        for (int j = k >> 1; j > 0; j >>= 1) {
            u64 o = shfl_xor64(v, j);
            bool takeMin = (((lane & j) == 0) == ((lane & k) == 0));
            if ((o < v) == takeMin) v = o;
        }
    }
}

// two independent sorts interleaved (2x ILP on the shfl chain)
__device__ __forceinline__ void bitonic_sort32_pair(u64& a, u64& b, int lane) {
#pragma unroll
    for (int k = 2; k <= 32; k <<= 1) {
#pragma unroll
        for (int j = k >> 1; j > 0; j >>= 1) {
            u64 oa = shfl_xor64(a, j);
            u64 ob = shfl_xor64(b, j);
            bool takeMin = (((lane & j) == 0) == ((lane & k) == 0));
            if ((oa < a) == takeMin) a = oa;
            if ((ob < b) == takeMin) b = ob;
        }
    }
}

// bitonic merge (input bitonic), ascending by lane
__device__ __forceinline__ void bitonic_merge32(u64& v, int lane) {
#pragma unroll
    for (int j = 16; j > 0; j >>= 1) {
        u64 o = shfl_xor64(v, j);
        bool takeMin = ((lane & j) == 0);
        if ((o < v) == takeMin) v = o;
    }
}

// insert key k into sorted-ascending L (drops old max). No-op if k >= L[31].
__device__ __forceinline__ void warp_insert(u64& L, u64 k, int lane) {
    unsigned mlt = __ballot_sync(FULLMASK, L < k);
    int p = __popc(mlt);
    u64 Ls = __shfl_up_sync(FULLMASK, L, 1);
    if (lane >= p) L = (lane == p) ? k : Ls;
}

// rare mid-loop flush: fold the 64-slot smem buffer into L, reset buffer
__device__ __forceinline__ void flush_smem(u64& L, bool& first, int& cnt,
                                           u64* buf, int lane) {
    __syncwarp();
    u64 A = buf[lane];
    u64 B = buf[32 + lane];
    bitonic_sort32_pair(A, B, lane);
    u64 brev = shfl_xor64(B, 31);
    u64 C = (A < brev) ? A : brev;
    bitonic_merge32(C, lane);              // top-32 of the 64 slots
    if (first) { L = C; first = false; }
    else {
        u64 crev = shfl_xor64(C, 31);
        L = (L < crev) ? L : crev;
        bitonic_merge32(L, lane);
    }
    buf[lane] = INVALID_KEY;
    buf[32 + lane] = INVALID_KEY;
    __syncwarp();
    cnt = 0;
}

// rare final path when a mid-loop flush happened: merge remaining buffer into L
__device__ __forceinline__ void finalize_merge(u64& L, int cnt, u64 A,
                                               const u64* buf, int lane) {
    if (cnt == 0) return;
    u64 arev = shfl_xor64(A, 31);
    L = (L < arev) ? L : arev;
    bitonic_merge32(L, lane);
    if (cnt > 32) {
        u64 B = buf[32 + lane];
        bitonic_sort32(B, lane);
        u64 brev = shfl_xor64(B, 31);
        L = (L < brev) ? L : brev;
        bitonic_merge32(L, lane);
    }
}

__global__ void __launch_bounds__(128)
radius_graph_kernel(const float* __restrict__ pos,
                    const int* __restrict__ batch,
                    float* __restrict__ out,
                    int N) {
    __shared__ u64 sbuf[4][2][64];
    const int wb = (int)(threadIdx.x >> 5);
    int w = (int)((blockIdx.x * blockDim.x + threadIdx.x) >> 5);
    int lane = threadIdx.x & 31;
    const int i0 = 2 * w;
    if (i0 >= N) return;
    const int i1 = i0 + 1;
    const bool has1 = (i1 < N);
    const int nk = N * KNB;
    const float D2T = __uint_as_float(D2_THRESH_BITS);
    const unsigned lmlt = (1u << lane) - 1u;

    sbuf[wb][0][lane] = INVALID_KEY; sbuf[wb][0][32 + lane] = INVALID_KEY;
    sbuf[wb][1][lane] = INVALID_KEY; sbuf[wb][1][32 + lane] = INVALID_KEY;
    __syncwarp();

    const float x0 = pos[3 * i0 + 0], y0 = pos[3 * i0 + 1], z0 = pos[3 * i0 + 2];
    const float sq0 = sumsq_xla(x0, y0, z0);
    const int b0 = batch[i0];

    float x1 = x0, y1 = y0, z1 = z0, sq1 = sq0;
    int b1 = b0;
    if (has1) {
        x1 = pos[3 * i1 + 0]; y1 = pos[3 * i1 + 1]; z1 = pos[3 * i1 + 2];
        sq1 = sumsq_xla(x1, y1, z1);
        b1 = batch[i1];
    }

    const int2 bounds = warp_bound_dual(batch, N, b0, b1, lane);
    const int LO = bounds.x, HI = bounds.y;
    const int hi0 = (b0 == b1) ? HI : i1;   // batch sorted: split exactly at i1
    const int lo1 = (b0 == b1) ? LO : i1;

    u64 L0 = INVALID_KEY, L1 = INVALID_KEY;
    int cnt0 = 0, cnt1 = 0;
    bool first0 = true, first1 = true;

    const int per = (HI - LO + 31) >> 5;

    // software pipeline: preload batch 0
    int j = LO + lane;
    bool inr = j < HI;
    float xj = 0.0f, yj = 0.0f, zj = 0.0f;
    if (inr) { xj = pos[3 * j + 0]; yj = pos[3 * j + 1]; zj = pos[3 * j + 2]; }

    for (int t = 0; t < per; t++) {
        // prefetch next batch before this batch's ballots (overlaps latency)
        int jn = j + 32;
        bool inn = (t + 1 < per) && (jn < HI);
        float xn = 0.0f, yn = 0.0f, zn = 0.0f;
        if (inn) { xn = pos[3 * jn + 0]; yn = pos[3 * jn + 1]; zn = pos[3 * jn + 2]; }

        u64 key0 = INVALID_KEY, key1 = INVALID_KEY;
        if (inr) {
            float sqj = sumsq_xla(xj, yj, zj);
            if (j < hi0 && j != i0) {
                float dot = __fmaf_rn(z0, zj, __fmaf_rn(y0, yj, __fmul_rn(x0, xj)));
                float d2 = __fsub_rn(__fadd_rn(sq0, sqj), __fmul_rn(2.0f, dot));
                if (d2 <= D2T) {   // exact equivalent of dist<=5.0
                    float dist = __fsqrt_rn(fmaxf(d2, 0.0f));
                    key0 = (((u64)__float_as_uint(dist)) << 32) | (unsigned int)j;
                }
            }
            if (has1 && j >= lo1 && j != i1) {
                float dot = __fmaf_rn(z1, zj, __fmaf_rn(y1, yj, __fmul_rn(x1, xj)));
                float d2 = __fsub_rn(__fadd_rn(sq1, sqj), __fmul_rn(2.0f, dot));
                if (d2 <= D2T) {
                    float dist = __fsqrt_rn(fmaxf(d2, 0.0f));
                    key1 = (((u64)__float_as_uint(dist)) << 32) | (unsigned int)j;
                }
            }
        }
        unsigned bal0 = __ballot_sync(FULLMASK, key0 != INVALID_KEY);
        unsigned bal1 = __ballot_sync(FULLMASK, key1 != INVALID_KEY);
        if (bal0) {
            int nv = __popc(bal0);
            if (cnt0 + nv > 64) flush_smem(L0, first0, cnt0, &sbuf[wb][0][0], lane);
            int r = __popc(bal0 & lmlt);
            if (key0 != INVALID_KEY) sbuf[wb][0][cnt0 + r] = key0;
            cnt0 += nv;
        }
        if (bal1) {
            int nv = __popc(bal1);
            if (cnt1 + nv > 64) flush_smem(L1, first1, cnt1, &sbuf[wb][1][0], lane);
            int r = __popc(bal1 & lmlt);
            if (key1 != INVALID_KEY) sbuf[wb][1][cnt1 + r] = key1;
            cnt1 += nv;
        }
        j = jn; inr = inn; xj = xn; yj = yn; zj = zn;
    }

    __syncwarp();
    u64 A0 = sbuf[wb][0][lane];
    u64 A1 = sbuf[wb][1][lane];
    bitonic_sort32_pair(A0, A1, lane);   // one interleaved sort covers both atoms

    if (first0 && first1) {
        // dominant path: no mid-loop flush happened for either atom
        if (cnt0 > 0) L0 = A0;
        if (cnt1 > 0) L1 = A1;
        int m0 = cnt0 > 32 ? cnt0 - 32 : 0;
        int m1 = cnt1 > 32 ? cnt1 - 32 : 0;
        int mm = m0 > m1 ? m0 : m1;
        for (int idx = 0; idx < mm; idx++) {      // interleaved tail inserts
            if (idx < m0) warp_insert(L0, sbuf[wb][0][32 + idx], lane);
            if (idx < m1) warp_insert(L1, sbuf[wb][1][32 + idx], lane);
        }
    } else {
        if (first0) {
            if (cnt0 > 0) L0 = A0;
            int m0 = cnt0 > 32 ? cnt0 - 32 : 0;
            for (int idx = 0; idx < m0; idx++)
                warp_insert(L0, sbuf[wb][0][32 + idx], lane);
        } else finalize_merge(L0, cnt0, A0, &sbuf[wb][0][0], lane);
        if (first1) {
            if (cnt1 > 0) L1 = A1;
            int m1 = cnt1 > 32 ? cnt1 - 32 : 0;
            for (int idx = 0; idx < m1; idx++)
                warp_insert(L1, sbuf[wb][1][32 + idx], lane);
        } else finalize_merge(L1, cnt1, A1, &sbuf[wb][1][0], lane);
    }

    // lane k owns output slot k: k-th nearest neighbor (exact top_k order)
    {
        const bool valid = (L0 != INVALID_KEY);
        const int jd = valid ? (int)(unsigned int)(L0 & 0xFFFFFFFFull) : i0;
        const int e = i0 * KNB + lane;
        float vx = 0.0f, vy = 0.0f, vz = 0.0f;
        if (valid) {
            vx = __fsub_rn(pos[3 * jd + 0], x0);
            vy = __fsub_rn(pos[3 * jd + 1], y0);
            vz = __fsub_rn(pos[3 * jd + 2], z0);
        }
        out[e]                  = (float)i0;
        out[nk + e]             = (float)jd;
        out[2 * nk + 3 * e + 0] = vx;
        out[2 * nk + 3 * e + 1] = vy;
        out[2 * nk + 3 * e + 2] = vz;
        out[5 * nk + e]         = valid ? 1.0f : 0.0f;
    }
    if (has1) {
        const bool valid = (L1 != INVALID_KEY);
        const int jd = valid ? (int)(unsigned int)(L1 & 0xFFFFFFFFull) : i1;
        const int e = i1 * KNB + lane;
        float vx = 0.0f, vy = 0.0f, vz = 0.0f;
        if (valid) {
            vx = __fsub_rn(pos[3 * jd + 0], x1);
            vy = __fsub_rn(pos[3 * jd + 1], y1);
            vz = __fsub_rn(pos[3 * jd + 2], z1);
        }
        out[e]                  = (float)i1;
        out[nk + e]             = (float)jd;
        out[2 * nk + 3 * e + 0] = vx;
        out[2 * nk + 3 * e + 1] = vy;
        out[2 * nk + 3 * e + 2] = vz;
        out[5 * nk + e]         = valid ? 1.0f : 0.0f;
    }
}

extern "C" void kernel_launch(void* const* d_in, const int* in_sizes, int n_in,
                              void* d_out, int out_size) {
    const float* pos = (const float*)d_in[0];
    const int* batch = (const int*)d_in[1];
    float* out = (float*)d_out;
    int N = in_sizes[1];            // batch has one entry per atom
    (void)n_in; (void)out_size;

    int nwarps = (N + 1) / 2;       // two atoms per warp
    const int warpsPerBlock = 4;    // 128 threads
    int blocks = (nwarps + warpsPerBlock - 1) / warpsPerBlock;
    radius_graph_kernel<<<blocks, warpsPerBlock * 32>>>(pos, batch, out, N);
}

// round 13
// speedup vs baseline: 1.0172x; 1.0172x over previous
#include <cuda_runtime.h>
#include <cuda_bf16.h>

#define KNB 32
#define INVALID_KEY 0xFFFFFFFFFFFFFFFFull
#define FULLMASK 0xFFFFFFFFu
// exact d2 threshold: dist<=5.0 with dist=__fsqrt_rn(d2)  <=>  d2 <= 25+2^-19
#define D2_THRESH_BITS 0x41C80001u

typedef unsigned long long u64;

// XLA-matching sum of squares: rn(rn(rn(x^2)+rn(y^2))+rn(z^2)), NO fma fusion
__device__ __forceinline__ float sumsq_xla(float x, float y, float z) {
    return __fadd_rn(__fadd_rn(__fmul_rn(x, x), __fmul_rn(y, y)), __fmul_rn(z, z));
}

__device__ __forceinline__ u64 shfl_xor64(u64 v, int m) { return __shfl_xor_sync(FULLMASK, v, m); }

// dual warp-parallel 32-ary search over the SAME molecule id b:
//   LO = first idx with batch[idx] >= b ; HI = first idx with batch[idx] > b
__device__ __forceinline__ int2 warp_bound_dual(const int* __restrict__ batch, int N,
                                                int b, int lane) {
    int l0 = 0, w0 = N, l1 = 0, w1 = N;
    while (w0 > 0 || w1 > 0) {
        int step0 = (w0 + 31) >> 5;
        int step1 = (w1 + 31) >> 5;
        int off0 = lane * step0;
        int off1 = lane * step1;
        bool in0 = (w0 > 0) && (off0 < w0);
        bool in1 = (w1 > 0) && (off1 < w1);
        int m0 = l0 + (in0 ? off0 : 0);
        int m1 = l1 + (in1 ? off1 : 0);
        int v0 = batch[m0];          // both probes in flight together
        int v1 = batch[m1];
        unsigned bal0 = __ballot_sync(FULLMASK, in0 && (v0 < b));
        unsigned bal1 = __ballot_sync(FULLMASK, in1 && (v1 <= b));
        if (w0 > 0) {
            int c = __popc(bal0);
            if (c == 0) w0 = 0;
            else {
                int newl = l0 + (c - 1) * step0 + 1;
                int ub = (c * step0 < w0) ? (l0 + c * step0) : (l0 + w0);
                w0 = ub - newl; l0 = newl;
            }
        }
        if (w1 > 0) {
            int c = __popc(bal1);
            if (c == 0) w1 = 0;
            else {
                int newl = l1 + (c - 1) * step1 + 1;
                int ub = (c * step1 < w1) ? (l1 + c * step1) : (l1 + w1);
                w1 = ub - newl; l1 = newl;
            }
        }
    }
    return make_int2(l0, l1);
}

// full bitonic sort of 32 keys, ascending by lane
__device__ __forceinline__ void bitonic_sort32(u64& v, int lane) {
#pragma unroll
    for (int k = 2; k <= 32; k <<= 1) {
#pragma unroll
        for (int j = k >> 1; j > 0; j >>= 1) {
            u64 o = shfl_xor64(v, j);
            bool takeMin = (((lane & j) == 0) == ((lane & k) == 0));
            if ((o < v) == takeMin) v = o;
        }
    }
}

// two independent sorts interleaved (2x ILP on the shfl chain)
__device__ __forceinline__ void bitonic_sort32_pair(u64& a, u64& b, int lane) {
#pragma unroll
    for (int k = 2; k <= 32; k <<= 1) {
#pragma unroll
        for (int j = k >> 1; j > 0; j >>= 1) {
            u64 oa = shfl_xor64(a, j);
            u64 ob = shfl_xor64(b, j);
            bool takeMin = (((lane & j) == 0) == ((lane & k) == 0));
            if ((oa < a) == takeMin) a = oa;
            if ((ob < b) == takeMin) b = ob;
        }
    }
}

// bitonic merge (input bitonic), ascending by lane
__device__ __forceinline__ void bitonic_merge32(u64& v, int lane) {
#pragma unroll
    for (int j = 16; j > 0; j >>= 1) {
        u64 o = shfl_xor64(v, j);
        bool takeMin = ((lane & j) == 0);
        if ((o < v) == takeMin) v = o;
    }
}

// insert key k into sorted-ascending L (drops old max). No-op if k >= L[31].
__device__ __forceinline__ void warp_insert(u64& L, u64 k, int lane) {
    unsigned mlt = __ballot_sync(FULLMASK, L < k);
    int p = __popc(mlt);
    u64 Ls = __shfl_up_sync(FULLMASK, L, 1);
    if (lane >= p) L = (lane == p) ? k : Ls;
}

// rare mid-loop flush: fold the 64-slot smem buffer into L, reset buffer
__device__ __forceinline__ void flush_smem(u64& L, bool& first, int& cnt,
                                           u64* buf, int lane) {
    __syncwarp();
    u64 A = buf[lane];
    u64 B = buf[32 + lane];
    bitonic_sort32_pair(A, B, lane);
    u64 brev = shfl_xor64(B, 31);
    u64 C = (A < brev) ? A : brev;
    bitonic_merge32(C, lane);              // top-32 of the 64 slots
    if (first) { L = C; first = false; }
    else {
        u64 crev = shfl_xor64(C, 31);
        L = (L < crev) ? L : crev;
        bitonic_merge32(L, lane);
    }
    buf[lane] = INVALID_KEY;
    buf[32 + lane] = INVALID_KEY;
    __syncwarp();
    cnt = 0;
}

// rare final path when a mid-loop flush happened: merge remaining buffer into L
__device__ __forceinline__ void finalize_merge(u64& L, int cnt, u64 A,
                                               const u64* buf, int lane) {
    if (cnt == 0) return;
    u64 arev = shfl_xor64(A, 31);
    L = (L < arev) ? L : arev;
    bitonic_merge32(L, lane);
    if (cnt > 32) {
        u64 B = buf[32 + lane];
        bitonic_sort32(B, lane);
        u64 brev = shfl_xor64(B, 31);
        L = (L < brev) ? L : brev;
        bitonic_merge32(L, lane);
    }
}

__global__ void __launch_bounds__(128)
radius_graph_kernel(const float* __restrict__ pos,
                    const int* __restrict__ batch,
                    float* __restrict__ out,
                    int N) {
    __shared__ u64 sbuf[4][64];
    const int wb = (int)(threadIdx.x >> 5);
    const int i = (int)((blockIdx.x * blockDim.x + threadIdx.x) >> 5);
    const int lane = threadIdx.x & 31;
    if (i >= N) return;
    const int nk = N * KNB;
    const float D2T = __uint_as_float(D2_THRESH_BITS);
    const unsigned lmlt = (1u << lane) - 1u;

    sbuf[wb][lane] = INVALID_KEY;
    sbuf[wb][32 + lane] = INVALID_KEY;
    __syncwarp();

    const float xi = pos[3 * i + 0], yi = pos[3 * i + 1], zi = pos[3 * i + 2];
    const float sqi = sumsq_xla(xi, yi, zi);
    const int b = batch[i];

    const int2 bounds = warp_bound_dual(batch, N, b, lane);
    const int LO = bounds.x, HI = bounds.y;

    u64 L = INVALID_KEY;
    int cnt = 0;
    bool first = true;

    const int per = (HI - LO + 31) >> 5;
    for (int t = 0; t < per; t++) {
        int j = LO + lane + (t << 5);
        u64 key = INVALID_KEY;
        if (j < HI && j != i) {
            float xj = pos[3 * j + 0];
            float yj = pos[3 * j + 1];
            float zj = pos[3 * j + 2];
            float sqj = sumsq_xla(xj, yj, zj);
            float dot = __fmaf_rn(zi, zj, __fmaf_rn(yi, yj, __fmul_rn(xi, xj)));
            float d2 = __fsub_rn(__fadd_rn(sqi, sqj), __fmul_rn(2.0f, dot));
            if (d2 <= D2T) {   // exact equivalent of dist<=5.0
                float dist = __fsqrt_rn(fmaxf(d2, 0.0f));
                key = (((u64)__float_as_uint(dist)) << 32) | (unsigned int)j;
            }
        }
        unsigned bal = __ballot_sync(FULLMASK, key != INVALID_KEY);
        if (bal) {
            int nv = __popc(bal);
            if (cnt + nv > 64) flush_smem(L, first, cnt, &sbuf[wb][0], lane);
            int r = __popc(bal & lmlt);
            if (key != INVALID_KEY) sbuf[wb][cnt + r] = key;
            cnt += nv;
        }
    }

    __syncwarp();
    u64 A = sbuf[wb][lane];
    bitonic_sort32(A, lane);

    if (first) {
        // dominant path: no mid-loop flush happened
        if (cnt > 0) L = A;
        int m = cnt > 32 ? cnt - 32 : 0;
        for (int idx = 0; idx < m; idx++)
            warp_insert(L, sbuf[wb][32 + idx], lane);
    } else {
        finalize_merge(L, cnt, A, &sbuf[wb][0], lane);
    }

    // lane k owns output slot k: k-th nearest neighbor (exact top_k order)
    const bool valid = (L != INVALID_KEY);
    const int jd = valid ? (int)(unsigned int)(L & 0xFFFFFFFFull) : i;
    const int e = i * KNB + lane;
    float vx = 0.0f, vy = 0.0f, vz = 0.0f;
    if (valid) {
        vx = __fsub_rn(pos[3 * jd + 0], xi);
        vy = __fsub_rn(pos[3 * jd + 1], yi);
        vz = __fsub_rn(pos[3 * jd + 2], zi);
    }
    out[e]                  = (float)i;            // src
    out[nk + e]             = (float)jd;           // dst
    out[2 * nk + 3 * e + 0] = vx;                  // edge_vec
    out[2 * nk + 3 * e + 1] = vy;
    out[2 * nk + 3 * e + 2] = vz;
    out[5 * nk + e]         = valid ? 1.0f : 0.0f; // mask
}

extern "C" void kernel_launch(void* const* d_in, const int* in_sizes, int n_in,
                              void* d_out, int out_size) {
    const float* pos = (const float*)d_in[0];
    const int* batch = (const int*)d_in[1];
    float* out = (float*)d_out;
    int N = in_sizes[1];            // batch has one entry per atom
    (void)n_in; (void)out_size;

    const int warpsPerBlock = 4;    // 128 threads; one atom per warp
    int blocks = (N + warpsPerBlock - 1) / warpsPerBlock;
    radius_graph_kernel<<<blocks, warpsPerBlock * 32>>>(pos, batch, out, N);
}